// round 8
// baseline (speedup 1.0000x reference)
#include <cuda_runtime.h>
#include <cuda_bf16.h>
#include <cstdint>

// ============================================================================
// xFuserMXFP4Linear: fake-MXFP4 (e2m1 + E8M0 per-1x32-block scale) quant of
// A[M,K] and W[N,K], then fp32 GEMM out = Aq @ Wq^T + bias.
//
// Toolchain emits PTX for plain sm_103 => no tcgen05/TMA. Baseline tensor
// path: cp.async + ldmatrix + mma.sync.m16n8k16 (bf16 in, fp32 accum).
// Dequantized MXFP4 values are exact in bf16 => rel_err ~0.
//
// R7: warp tile 64x64 (halves LDSM traffic/FLOP), CTA 128x128 with 4 warps,
// __launch_bounds__(128,2) to force 2 CTAs/SM for phase staggering.
// ============================================================================

// ---------------- device scratch (allowed: __device__ globals) --------------
__device__ __nv_bfloat16 g_Aq[8192u * 2048u];   // 32 MB
__device__ __nv_bfloat16 g_Wq[2048u * 2048u];   // 8 MB

// ============================================================================
// PTX helpers (baseline ISA only)
// ============================================================================
__device__ __forceinline__ uint32_t smem_to_u32(const void* smem_ptr) {
    uint32_t addr;
    asm("{ .reg .u64 tmp; cvta.to.shared.u64 tmp, %1; cvt.u32.u64 %0, tmp; }"
        : "=r"(addr) : "l"(smem_ptr));
    return addr;
}

#define CP_ASYNC16(smem_u32, gptr) \
    asm volatile("cp.async.cg.shared.global [%0], [%1], 16;\n" \
                 :: "r"(smem_u32), "l"(gptr))

#define CP_COMMIT() asm volatile("cp.async.commit_group;\n" ::: "memory")
#define CP_WAIT(n)  asm volatile("cp.async.wait_group %0;\n" :: "n"(n) : "memory")

__device__ __forceinline__ void ldsm_x4(uint32_t* r, uint32_t addr) {
    asm volatile("ldmatrix.sync.aligned.m8n8.x4.shared.b16 {%0,%1,%2,%3}, [%4];"
                 : "=r"(r[0]), "=r"(r[1]), "=r"(r[2]), "=r"(r[3]) : "r"(addr));
}

__device__ __forceinline__ void mma_16816(float* c, const uint32_t* a,
                                          const uint32_t* b) {
    asm volatile(
        "mma.sync.aligned.m16n8k16.row.col.f32.bf16.bf16.f32 "
        "{%0,%1,%2,%3}, {%4,%5,%6,%7}, {%8,%9}, {%0,%1,%2,%3};"
        : "+f"(c[0]), "+f"(c[1]), "+f"(c[2]), "+f"(c[3])
        : "r"(a[0]), "r"(a[1]), "r"(a[2]), "r"(a[3]), "r"(b[0]), "r"(b[1]));
}

// ============================================================================
// Quantize kernel (fused A+W): 8 threads per 1x32 block, one float4/thread.
// Coalesced loads/stores; amax via 3x shfl.bfly within the lane-aligned
// 8-thread group. Exact reference math (frexpf/ldexpf/rintf).
// ============================================================================
__device__ __forceinline__ void quant_quad(const float* __restrict__ x,
                                           __nv_bfloat16* __restrict__ out,
                                           int t)
{
    float4 v = reinterpret_cast<const float4*>(x)[t];
    float amax = fmaxf(fmaxf(fabsf(v.x), fabsf(v.y)),
                       fmaxf(fabsf(v.z), fabsf(v.w)));
    amax = fmaxf(amax, __shfl_xor_sync(0xFFFFFFFFu, amax, 1));
    amax = fmaxf(amax, __shfl_xor_sync(0xFFFFFFFFu, amax, 2));
    amax = fmaxf(amax, __shfl_xor_sync(0xFFFFFFFFu, amax, 4));

    float scale = 1.f, inv = 1.f;
    bool use_inv = true;
    if (amax > 0.f) {
        int e;
        frexpf(fmaxf(amax, 1.17549435e-38f), &e);   // amax = m*2^e, m in [0.5,1)
        scale = ldexpf(1.f, e - 3);                 // 2^(floor(log2 amax) - 2)
        use_inv = (e >= -120);
        inv = use_inv ? ldexpf(1.f, 3 - e) : 1.f;
    }

    float in4[4] = {v.x, v.y, v.z, v.w};
    __nv_bfloat16 q[4];
#pragma unroll
    for (int j = 0; j < 4; j++) {
        float qv = use_inv ? in4[j] * inv : in4[j] / scale;
        qv = fminf(fmaxf(qv, -6.f), 6.f);
        float aq = fabsf(qv);
        // e2m1 ulp: 0.5 on [0,2), 1 on [2,4), 2 on [4,6]
        float lsb  = aq < 2.f ? 0.5f : (aq < 4.f ? 1.f : 2.f);
        float rlsb = aq < 2.f ? 2.f  : (aq < 4.f ? 1.f : 0.5f);
        float qr = rintf(qv * rlsb) * lsb;          // RNE onto fp4 grid (exact)
        q[j] = __float2bfloat16(qr * scale);        // exact in bf16
    }
    reinterpret_cast<uint2*>(out)[t] = *reinterpret_cast<const uint2*>(q);
}

__global__ void __launch_bounds__(256) quant_mxfp4_fused_kernel(
    const float* __restrict__ a, __nv_bfloat16* __restrict__ aq,
    const float* __restrict__ w, __nv_bfloat16* __restrict__ wq,
    int aquads, int wquads)
{
    int t = blockIdx.x * blockDim.x + threadIdx.x;
    if (t < aquads)                quant_quad(a, aq, t);
    else if (t < aquads + wquads)  quant_quad(w, wq, t - aquads);
}

// ============================================================================
// bf16 GEMM via mma.sync: out[M,N] = Aq[M,K] @ Wq[N,K]^T + bias
// CTA tile 128x128x32, 128 threads (4 warps, 2x2), warp tile 64x64.
// 3-stage cp.async ring, one __syncthreads per K-step. 2 CTAs/SM stagger
// their barrier/LDSM phases. Smem rows padded to 80B (conflict-free ldmatrix).
// ============================================================================
static constexpr int BM = 128;
static constexpr int BN = 128;
static constexpr int BK = 32;            // bf16 elems per K-stage
static constexpr int STAGES = 3;
static constexpr int ROW_H = 40;         // smem row stride in halves (80 B)
static constexpr int TILE_B = 128 * ROW_H * 2;        // 10240 bytes
static constexpr int STAGE_B = 2 * TILE_B;            // A + B = 20480 bytes
static constexpr int SMEM_TOTAL = STAGES * STAGE_B;   // 61440 bytes

__global__ void __launch_bounds__(128, 2) mxfp4_gemm_kernel(
    const __nv_bfloat16* __restrict__ A,   // [M,K]
    const __nv_bfloat16* __restrict__ W,   // [N,K]
    const float* __restrict__ bias,        // [N]
    float* __restrict__ out,               // [M,N]
    int M, int N, int K)
{
    extern __shared__ __align__(16) char smem[];
    const uint32_t sb = smem_to_u32(smem);

    const int tid = threadIdx.x;
    const int wid = tid >> 5;
    const int lid = tid & 31;
    const int warp_m = wid & 1;           // 0..1 -> 64-row slab
    const int warp_n = wid >> 1;          // 0..1 -> 64-col slab
    const int m0 = blockIdx.y * BM;
    const int n0 = blockIdx.x * BN;

    // cp.async mapping: 1024 16B-chunks per stage (A 512 + B 512),
    // 8 per thread. Column chunk fixed per thread; 4 row groups each.
    const int cc = tid & 3;               // 16B chunk within 64B row
    const int rr = tid >> 2;              // base row 0..31

    const __nv_bfloat16* Abase = A + (size_t)m0 * K;
    const __nv_bfloat16* Wbase = W + (size_t)n0 * K;

    auto prefetch = [&](int stage, int kk) {
        uint32_t sA = sb + stage * STAGE_B;
        uint32_t sB = sA + TILE_B;
#pragma unroll
        for (int i = 0; i < 4; i++) {
            int r = rr + i * 32;
            CP_ASYNC16(sA + (uint32_t)(r * ROW_H + cc * 8) * 2,
                       Abase + (size_t)r * K + kk + cc * 8);
            CP_ASYNC16(sB + (uint32_t)(r * ROW_H + cc * 8) * 2,
                       Wbase + (size_t)r * K + kk + cc * 8);
        }
    };

    float acc[4][8][4];
#pragma unroll
    for (int tm = 0; tm < 4; tm++)
#pragma unroll
        for (int nt = 0; nt < 8; nt++)
#pragma unroll
            for (int j = 0; j < 4; j++) acc[tm][nt][j] = 0.f;

    const int aRowBase = warp_m * 64;
    const int bRowBase = warp_n * 64;
    const int nK = K / BK;

    // prologue: fill STAGES-1 stages
#pragma unroll
    for (int s = 0; s < STAGES - 1; s++) {
        prefetch(s, s * BK);
        CP_COMMIT();
    }

    int cur = 0;
    for (int kt = 0; kt < nK; kt++) {
        CP_WAIT(STAGES - 2);
        __syncthreads();

        // prefetch next stage right away (target stage consumed at kt-1,
        // its fragments were register-resident before the last barrier)
        if (kt + STAGES - 1 < nK) {
            int wstage = cur + STAGES - 1;
            if (wstage >= STAGES) wstage -= STAGES;
            prefetch(wstage, (kt + STAGES - 1) * BK);
        }
        CP_COMMIT();

        const uint32_t sA = sb + cur * STAGE_B;
        const uint32_t sBm = sA + TILE_B;

        // ---- process two k=16 substeps; fragments per substep only ----
#pragma unroll
        for (int ks = 0; ks < 2; ks++) {
            uint32_t af[4][4];   // [tm][4]
            uint32_t bf[8][2];   // [nt][2]
#pragma unroll
            for (int tm = 0; tm < 4; tm++) {
                int row = aRowBase + tm * 16 + (lid & 15);
                int col = ks * 16 + (lid >> 4) * 8;
                ldsm_x4(af[tm], sA + (uint32_t)(row * ROW_H + col) * 2);
            }
#pragma unroll
            for (int ntp = 0; ntp < 4; ntp++) {
                int g = lid >> 3;
                int row = bRowBase + ntp * 16 + (g >> 1) * 8 + (lid & 7);
                int col = ks * 16 + (g & 1) * 8;
                uint32_t r[4];
                ldsm_x4(r, sBm + (uint32_t)(row * ROW_H + col) * 2);
                bf[2 * ntp][0]     = r[0];
                bf[2 * ntp][1]     = r[1];
                bf[2 * ntp + 1][0] = r[2];
                bf[2 * ntp + 1][1] = r[3];
            }

#pragma unroll
            for (int tm = 0; tm < 4; tm++)
#pragma unroll
                for (int nt = 0; nt < 8; nt++)
                    mma_16816(acc[tm][nt], af[tm], bf[nt]);
        }

        if (++cur == STAGES) cur = 0;
    }

    // ---- epilogue: fused bias, float2 stores ----
    const int g = lid >> 2;               // 0..7
    const int tc = (lid & 3) * 2;         // 0,2,4,6
#pragma unroll
    for (int nt = 0; nt < 8; nt++) {
        int col = n0 + warp_n * 64 + nt * 8 + tc;
        float2 bv = *reinterpret_cast<const float2*>(bias + col);
#pragma unroll
        for (int tm = 0; tm < 4; tm++) {
            int row = m0 + warp_m * 64 + tm * 16 + g;
            float2 v0 = { acc[tm][nt][0] + bv.x, acc[tm][nt][1] + bv.y };
            float2 v1 = { acc[tm][nt][2] + bv.x, acc[tm][nt][3] + bv.y };
            *reinterpret_cast<float2*>(out + (size_t)row * N + col) = v0;
            *reinterpret_cast<float2*>(out + (size_t)(row + 8) * N + col) = v1;
        }
    }
}

// ============================================================================
// launch
// ============================================================================
extern "C" void kernel_launch(void* const* d_in, const int* in_sizes, int n_in,
                              void* d_out, int out_size)
{
    const float* inp  = (const float*)d_in[0];   // [B*S, K] fp32
    const float* w    = (const float*)d_in[1];   // [N, K]  fp32
    const float* bias = (const float*)d_in[2];   // [N]     fp32
    float* out = (float*)d_out;

    int N = in_sizes[2];
    int K = in_sizes[1] / N;
    int M = (int)((long long)in_sizes[0] / K);

    __nv_bfloat16 *Aq, *Wq;
    cudaGetSymbolAddress((void**)&Aq, g_Aq);
    cudaGetSymbolAddress((void**)&Wq, g_Wq);

    int aquads = (int)((long long)M * K / 4);
    int wquads = (int)((long long)N * K / 4);
    int tquads = aquads + wquads;
    quant_mxfp4_fused_kernel<<<(tquads + 255) / 256, 256>>>(
        inp, Aq, w, Wq, aquads, wquads);

    static bool attr_set = false;
    if (!attr_set) {
        cudaFuncSetAttribute(mxfp4_gemm_kernel,
                             cudaFuncAttributeMaxDynamicSharedMemorySize,
                             SMEM_TOTAL);
        attr_set = true;
    }

    dim3 grid(N / BN, M / BM);
    mxfp4_gemm_kernel<<<grid, 128, SMEM_TOTAL>>>(Aq, Wq, bias, out, M, N, K);
}

// round 9
// speedup vs baseline: 1.2301x; 1.2301x over previous
#include <cuda_runtime.h>
#include <cuda_bf16.h>
#include <cstdint>

// ============================================================================
// xFuserMXFP4Linear: fake-MXFP4 (e2m1 + E8M0 per-1x32-block scale) quant of
// A[M,K] and W[N,K], then fp32 GEMM out = Aq @ Wq^T + bias.
//
// Toolchain emits PTX for plain sm_103 => no tcgen05/TMA. Baseline tensor
// path: cp.async + ldmatrix + mma.sync.m16n8k16 (bf16 in, fp32 accum).
// Dequantized MXFP4 values are exact in bf16 => rel_err ~0.
//
// R8: CTA 128x256, 8 warps (2x4) of 64x64; 4-stage cp.async ring; register
// double-buffered fragments (LDSM for ks+1 overlaps MMA of ks). Quant uses
// bit-twiddled exponent math instead of frexpf/ldexpf libdevice calls.
// ============================================================================

// ---------------- device scratch (allowed: __device__ globals) --------------
__device__ __nv_bfloat16 g_Aq[8192u * 2048u];   // 32 MB
__device__ __nv_bfloat16 g_Wq[2048u * 2048u];   // 8 MB

// ============================================================================
// PTX helpers (baseline ISA only)
// ============================================================================
__device__ __forceinline__ uint32_t smem_to_u32(const void* smem_ptr) {
    uint32_t addr;
    asm("{ .reg .u64 tmp; cvta.to.shared.u64 tmp, %1; cvt.u32.u64 %0, tmp; }"
        : "=r"(addr) : "l"(smem_ptr));
    return addr;
}

#define CP_ASYNC16(smem_u32, gptr) \
    asm volatile("cp.async.cg.shared.global [%0], [%1], 16;\n" \
                 :: "r"(smem_u32), "l"(gptr))

#define CP_COMMIT() asm volatile("cp.async.commit_group;\n" ::: "memory")
#define CP_WAIT(n)  asm volatile("cp.async.wait_group %0;\n" :: "n"(n) : "memory")

__device__ __forceinline__ void ldsm_x4(uint32_t* r, uint32_t addr) {
    asm volatile("ldmatrix.sync.aligned.m8n8.x4.shared.b16 {%0,%1,%2,%3}, [%4];"
                 : "=r"(r[0]), "=r"(r[1]), "=r"(r[2]), "=r"(r[3]) : "r"(addr));
}

__device__ __forceinline__ void mma_16816(float* c, const uint32_t* a,
                                          const uint32_t* b) {
    asm volatile(
        "mma.sync.aligned.m16n8k16.row.col.f32.bf16.bf16.f32 "
        "{%0,%1,%2,%3}, {%4,%5,%6,%7}, {%8,%9}, {%0,%1,%2,%3};"
        : "+f"(c[0]), "+f"(c[1]), "+f"(c[2]), "+f"(c[3])
        : "r"(a[0]), "r"(a[1]), "r"(a[2]), "r"(a[3]), "r"(b[0]), "r"(b[1]));
}

// ============================================================================
// Quantize kernel (fused A+W): 8 threads per 1x32 block, one float4/thread.
// amax exponent extracted from IEEE bits (no libdevice frexpf/ldexpf on the
// hot path; exact — power-of-two scale construction is pure bit arithmetic).
// Slow path only for denormal/extreme amax (exactness preserved).
// ============================================================================
__device__ __forceinline__ void quant_quad(const float* __restrict__ x,
                                           __nv_bfloat16* __restrict__ out,
                                           int t)
{
    float4 v = reinterpret_cast<const float4*>(x)[t];
    float amax = fmaxf(fmaxf(fabsf(v.x), fabsf(v.y)),
                       fmaxf(fabsf(v.z), fabsf(v.w)));
    amax = fmaxf(amax, __shfl_xor_sync(0xFFFFFFFFu, amax, 1));
    amax = fmaxf(amax, __shfl_xor_sync(0xFFFFFFFFu, amax, 2));
    amax = fmaxf(amax, __shfl_xor_sync(0xFFFFFFFFu, amax, 4));

    float scale = 1.f, inv = 1.f;
    if (amax > 0.f) {
        uint32_t bits = __float_as_uint(amax);
        int e = (int)(bits >> 23);          // biased exponent
        if (e >= 3 && e <= 254) {
            // floor(log2(amax)) = e-127; scale = 2^(e-127-2); inv = 1/scale
            scale = __uint_as_float((uint32_t)(e - 2) << 23);
            inv   = __uint_as_float((uint32_t)(256 - e) << 23);
        } else {
            // denormal or near-overflow amax: exact libdevice fallback
            int ee;
            frexpf(fmaxf(amax, 1.17549435e-38f), &ee);
            scale = ldexpf(1.f, ee - 3);
            inv   = (ee >= -120) ? ldexpf(1.f, 3 - ee) : 0.f;
            if (inv == 0.f) {               // extreme underflow: divide path
                float in4[4] = {v.x, v.y, v.z, v.w};
                __nv_bfloat16 q[4];
#pragma unroll
                for (int j = 0; j < 4; j++) {
                    float qv = fminf(fmaxf(in4[j] / scale, -6.f), 6.f);
                    float aq = fabsf(qv);
                    float lsb  = aq < 2.f ? 0.5f : (aq < 4.f ? 1.f : 2.f);
                    float rlsb = aq < 2.f ? 2.f  : (aq < 4.f ? 1.f : 0.5f);
                    q[j] = __float2bfloat16(rintf(qv * rlsb) * lsb * scale);
                }
                reinterpret_cast<uint2*>(out)[t] =
                    *reinterpret_cast<const uint2*>(q);
                return;
            }
        }
    }

    float in4[4] = {v.x, v.y, v.z, v.w};
    __nv_bfloat16 q[4];
#pragma unroll
    for (int j = 0; j < 4; j++) {
        float qv = fminf(fmaxf(in4[j] * inv, -6.f), 6.f);
        float aq = fabsf(qv);
        // e2m1 ulp: 0.5 on [0,2), 1 on [2,4), 2 on [4,6]
        float lsb  = aq < 2.f ? 0.5f : (aq < 4.f ? 1.f : 2.f);
        float rlsb = aq < 2.f ? 2.f  : (aq < 4.f ? 1.f : 0.5f);
        float qr = rintf(qv * rlsb) * lsb;          // RNE onto fp4 grid (exact)
        q[j] = __float2bfloat16(qr * scale);        // exact in bf16
    }
    reinterpret_cast<uint2*>(out)[t] = *reinterpret_cast<const uint2*>(q);
}

__global__ void __launch_bounds__(256) quant_mxfp4_fused_kernel(
    const float* __restrict__ a, __nv_bfloat16* __restrict__ aq,
    const float* __restrict__ w, __nv_bfloat16* __restrict__ wq,
    int aquads, int wquads)
{
    int t = blockIdx.x * blockDim.x + threadIdx.x;
    if (t < aquads)                quant_quad(a, aq, t);
    else if (t < aquads + wquads)  quant_quad(w, wq, t - aquads);
}

// ============================================================================
// bf16 GEMM via mma.sync: out[M,N] = Aq[M,K] @ Wq[N,K]^T + bias
// CTA tile 128x256x32, 256 threads (8 warps, 2x4), warp tile 64x64.
// 4-stage cp.async ring, one __syncthreads per K-step, register
// double-buffered fragments across the two k=16 substeps.
// Smem rows padded to 80B (conflict-free ldmatrix).
// ============================================================================
static constexpr int BM = 128;
static constexpr int BN = 256;
static constexpr int BK = 32;            // bf16 elems per K-stage
static constexpr int STAGES = 4;
static constexpr int ROW_H = 40;         // smem row stride in halves (80 B)
static constexpr int TILEA_B = BM * ROW_H * 2;        // 10240 bytes
static constexpr int TILEB_B = BN * ROW_H * 2;        // 20480 bytes
static constexpr int STAGE_B = TILEA_B + TILEB_B;     // 30720 bytes
static constexpr int SMEM_TOTAL = STAGES * STAGE_B;   // 122880 bytes

__global__ void __launch_bounds__(256, 1) mxfp4_gemm_kernel(
    const __nv_bfloat16* __restrict__ A,   // [M,K]
    const __nv_bfloat16* __restrict__ W,   // [N,K]
    const float* __restrict__ bias,        // [N]
    float* __restrict__ out,               // [M,N]
    int M, int N, int K)
{
    extern __shared__ __align__(16) char smem[];
    const uint32_t sb = smem_to_u32(smem);

    const int tid = threadIdx.x;
    const int wid = tid >> 5;
    const int lid = tid & 31;
    const int warp_m = wid & 1;           // 0..1 -> 64-row slab
    const int warp_n = wid >> 1;          // 0..3 -> 64-col slab
    const int m0 = blockIdx.y * BM;
    const int n0 = blockIdx.x * BN;

    // cp.async: A 512 chunks (2/thread), B 1024 chunks (4/thread)
    const int cc = tid & 3;               // 16B chunk within 64B row
    const int rr = tid >> 2;              // base row 0..63

    const __nv_bfloat16* Abase = A + (size_t)m0 * K;
    const __nv_bfloat16* Wbase = W + (size_t)n0 * K;

    auto prefetch = [&](int stage, int kk) {
        uint32_t sA = sb + stage * STAGE_B;
        uint32_t sB = sA + TILEA_B;
#pragma unroll
        for (int i = 0; i < 2; i++) {
            int r = rr + i * 64;
            CP_ASYNC16(sA + (uint32_t)(r * ROW_H + cc * 8) * 2,
                       Abase + (size_t)r * K + kk + cc * 8);
        }
#pragma unroll
        for (int i = 0; i < 4; i++) {
            int r = rr + i * 64;
            CP_ASYNC16(sB + (uint32_t)(r * ROW_H + cc * 8) * 2,
                       Wbase + (size_t)r * K + kk + cc * 8);
        }
    };

    float acc[4][8][4];
#pragma unroll
    for (int tm = 0; tm < 4; tm++)
#pragma unroll
        for (int nt = 0; nt < 8; nt++)
#pragma unroll
            for (int j = 0; j < 4; j++) acc[tm][nt][j] = 0.f;

    const int aRowBase = warp_m * 64;
    const int bRowBase = warp_n * 64;
    const int nK = K / BK;

    // fragment loader for one k=16 substep of stage 'base' addresses
    auto load_frags = [&](uint32_t sA, uint32_t sBm, int ks,
                          uint32_t af[4][4], uint32_t bf[8][2]) {
#pragma unroll
        for (int tm = 0; tm < 4; tm++) {
            int row = aRowBase + tm * 16 + (lid & 15);
            int col = ks * 16 + (lid >> 4) * 8;
            ldsm_x4(af[tm], sA + (uint32_t)(row * ROW_H + col) * 2);
        }
#pragma unroll
        for (int ntp = 0; ntp < 4; ntp++) {
            int g = lid >> 3;
            int row = bRowBase + ntp * 16 + (g >> 1) * 8 + (lid & 7);
            int col = ks * 16 + (g & 1) * 8;
            uint32_t r[4];
            ldsm_x4(r, sBm + (uint32_t)(row * ROW_H + col) * 2);
            bf[2 * ntp][0]     = r[0];
            bf[2 * ntp][1]     = r[1];
            bf[2 * ntp + 1][0] = r[2];
            bf[2 * ntp + 1][1] = r[3];
        }
    };

    // prologue: fill STAGES-1 stages
#pragma unroll
    for (int s = 0; s < STAGES - 1; s++) {
        prefetch(s, s * BK);
        CP_COMMIT();
    }

    int cur = 0;
    for (int kt = 0; kt < nK; kt++) {
        CP_WAIT(STAGES - 2);
        __syncthreads();

        // prefetch the stage consumed at kt-1 (drained: BAR.SYNC ordered its
        // LDSM reads before this point for all warps)
        if (kt + STAGES - 1 < nK) {
            int wstage = cur + STAGES - 1;
            if (wstage >= STAGES) wstage -= STAGES;
            prefetch(wstage, (kt + STAGES - 1) * BK);
        }
        CP_COMMIT();

        const uint32_t sA = sb + cur * STAGE_B;
        const uint32_t sBm = sA + TILEA_B;

        // double-buffered fragments: load ks=0, then overlap load ks=1 with
        // the ks=0 MMA burst
        uint32_t af[2][4][4];
        uint32_t bf[2][8][2];
        load_frags(sA, sBm, 0, af[0], bf[0]);
        load_frags(sA, sBm, 1, af[1], bf[1]);

#pragma unroll
        for (int ks = 0; ks < 2; ks++)
#pragma unroll
            for (int tm = 0; tm < 4; tm++)
#pragma unroll
                for (int nt = 0; nt < 8; nt++)
                    mma_16816(acc[tm][nt], af[ks][tm], bf[ks][nt]);

        if (++cur == STAGES) cur = 0;
    }

    // ---- epilogue: fused bias, float2 stores ----
    const int g = lid >> 2;               // 0..7
    const int tc = (lid & 3) * 2;         // 0,2,4,6
#pragma unroll
    for (int nt = 0; nt < 8; nt++) {
        int col = n0 + warp_n * 64 + nt * 8 + tc;
        float2 bv = *reinterpret_cast<const float2*>(bias + col);
#pragma unroll
        for (int tm = 0; tm < 4; tm++) {
            int row = m0 + warp_m * 64 + tm * 16 + g;
            float2 v0 = { acc[tm][nt][0] + bv.x, acc[tm][nt][1] + bv.y };
            float2 v1 = { acc[tm][nt][2] + bv.x, acc[tm][nt][3] + bv.y };
            *reinterpret_cast<float2*>(out + (size_t)row * N + col) = v0;
            *reinterpret_cast<float2*>(out + (size_t)(row + 8) * N + col) = v1;
        }
    }
}

// ============================================================================
// launch
// ============================================================================
extern "C" void kernel_launch(void* const* d_in, const int* in_sizes, int n_in,
                              void* d_out, int out_size)
{
    const float* inp  = (const float*)d_in[0];   // [B*S, K] fp32
    const float* w    = (const float*)d_in[1];   // [N, K]  fp32
    const float* bias = (const float*)d_in[2];   // [N]     fp32
    float* out = (float*)d_out;

    int N = in_sizes[2];
    int K = in_sizes[1] / N;
    int M = (int)((long long)in_sizes[0] / K);

    __nv_bfloat16 *Aq, *Wq;
    cudaGetSymbolAddress((void**)&Aq, g_Aq);
    cudaGetSymbolAddress((void**)&Wq, g_Wq);

    int aquads = (int)((long long)M * K / 4);
    int wquads = (int)((long long)N * K / 4);
    int tquads = aquads + wquads;
    quant_mxfp4_fused_kernel<<<(tquads + 255) / 256, 256>>>(
        inp, Aq, w, Wq, aquads, wquads);

    static bool attr_set = false;
    if (!attr_set) {
        cudaFuncSetAttribute(mxfp4_gemm_kernel,
                             cudaFuncAttributeMaxDynamicSharedMemorySize,
                             SMEM_TOTAL);
        attr_set = true;
    }

    dim3 grid(N / BN, M / BM);
    mxfp4_gemm_kernel<<<grid, 256, SMEM_TOTAL>>>(Aq, Wq, bias, out, M, N, K);
}

// round 10
// speedup vs baseline: 1.2800x; 1.0406x over previous
#include <cuda_runtime.h>
#include <cuda_bf16.h>
#include <cstdint>

// ============================================================================
// xFuserMXFP4Linear: fake-MXFP4 (e2m1 + E8M0 per-1x32-block scale) quant of
// A[M,K] and W[N,K], then fp32 GEMM out = Aq @ Wq^T + bias.
//
// Toolchain emits PTX for plain sm_103 => no tcgen05/TMA. Baseline tensor
// path: cp.async + ldmatrix + mma.sync.m16n8k16 (bf16 in, fp32 accum).
// Dequantized MXFP4 values are exact in bf16 => rel_err ~0.
//
// R9: cross-barrier fragment software pipeline. Every LDSM burst is followed
// by an independent MMA burst (fragments from the previous substep/stage), so
// LDSM latency, barrier latency and cp.async issue all hide under tensor
// work. 5-stage cp.async ring, prefetch after barrier, CP_WAIT(STAGES-3).
// ============================================================================

// ---------------- device scratch (allowed: __device__ globals) --------------
__device__ __nv_bfloat16 g_Aq[8192u * 2048u];   // 32 MB
__device__ __nv_bfloat16 g_Wq[2048u * 2048u];   // 8 MB

// ============================================================================
// PTX helpers (baseline ISA only)
// ============================================================================
__device__ __forceinline__ uint32_t smem_to_u32(const void* smem_ptr) {
    uint32_t addr;
    asm("{ .reg .u64 tmp; cvta.to.shared.u64 tmp, %1; cvt.u32.u64 %0, tmp; }"
        : "=r"(addr) : "l"(smem_ptr));
    return addr;
}

#define CP_ASYNC16(smem_u32, gptr) \
    asm volatile("cp.async.cg.shared.global [%0], [%1], 16;\n" \
                 :: "r"(smem_u32), "l"(gptr))

#define CP_COMMIT() asm volatile("cp.async.commit_group;\n" ::: "memory")
#define CP_WAIT(n)  asm volatile("cp.async.wait_group %0;\n" :: "n"(n) : "memory")

__device__ __forceinline__ void ldsm_x4(uint32_t* r, uint32_t addr) {
    asm volatile("ldmatrix.sync.aligned.m8n8.x4.shared.b16 {%0,%1,%2,%3}, [%4];"
                 : "=r"(r[0]), "=r"(r[1]), "=r"(r[2]), "=r"(r[3]) : "r"(addr));
}

__device__ __forceinline__ void mma_16816(float* c, const uint32_t* a,
                                          const uint32_t* b) {
    asm volatile(
        "mma.sync.aligned.m16n8k16.row.col.f32.bf16.bf16.f32 "
        "{%0,%1,%2,%3}, {%4,%5,%6,%7}, {%8,%9}, {%0,%1,%2,%3};"
        : "+f"(c[0]), "+f"(c[1]), "+f"(c[2]), "+f"(c[3])
        : "r"(a[0]), "r"(a[1]), "r"(a[2]), "r"(a[3]), "r"(b[0]), "r"(b[1]));
}

// ============================================================================
// Quantize kernel (fused A+W): 8 threads per 1x32 block, one float4/thread.
// amax exponent from IEEE bits (exact; libdevice fallback for denormal/edge).
// ============================================================================
__device__ __forceinline__ void quant_quad(const float* __restrict__ x,
                                           __nv_bfloat16* __restrict__ out,
                                           int t)
{
    float4 v = reinterpret_cast<const float4*>(x)[t];
    float amax = fmaxf(fmaxf(fabsf(v.x), fabsf(v.y)),
                       fmaxf(fabsf(v.z), fabsf(v.w)));
    amax = fmaxf(amax, __shfl_xor_sync(0xFFFFFFFFu, amax, 1));
    amax = fmaxf(amax, __shfl_xor_sync(0xFFFFFFFFu, amax, 2));
    amax = fmaxf(amax, __shfl_xor_sync(0xFFFFFFFFu, amax, 4));

    float scale = 1.f, inv = 1.f;
    if (amax > 0.f) {
        uint32_t bits = __float_as_uint(amax);
        int e = (int)(bits >> 23);          // biased exponent
        if (e >= 3 && e <= 254) {
            // floor(log2(amax)) = e-127; scale = 2^(e-127-2); inv = 1/scale
            scale = __uint_as_float((uint32_t)(e - 2) << 23);
            inv   = __uint_as_float((uint32_t)(256 - e) << 23);
        } else {
            // denormal or near-overflow amax: exact libdevice fallback
            int ee;
            frexpf(fmaxf(amax, 1.17549435e-38f), &ee);
            scale = ldexpf(1.f, ee - 3);
            inv   = (ee >= -120) ? ldexpf(1.f, 3 - ee) : 0.f;
            if (inv == 0.f) {               // extreme underflow: divide path
                float in4[4] = {v.x, v.y, v.z, v.w};
                __nv_bfloat16 q[4];
#pragma unroll
                for (int j = 0; j < 4; j++) {
                    float qv = fminf(fmaxf(in4[j] / scale, -6.f), 6.f);
                    float aq = fabsf(qv);
                    float lsb  = aq < 2.f ? 0.5f : (aq < 4.f ? 1.f : 2.f);
                    float rlsb = aq < 2.f ? 2.f  : (aq < 4.f ? 1.f : 0.5f);
                    q[j] = __float2bfloat16(rintf(qv * rlsb) * lsb * scale);
                }
                reinterpret_cast<uint2*>(out)[t] =
                    *reinterpret_cast<const uint2*>(q);
                return;
            }
        }
    }

    float in4[4] = {v.x, v.y, v.z, v.w};
    __nv_bfloat16 q[4];
#pragma unroll
    for (int j = 0; j < 4; j++) {
        float qv = fminf(fmaxf(in4[j] * inv, -6.f), 6.f);
        float aq = fabsf(qv);
        // e2m1 ulp: 0.5 on [0,2), 1 on [2,4), 2 on [4,6]
        float lsb  = aq < 2.f ? 0.5f : (aq < 4.f ? 1.f : 2.f);
        float rlsb = aq < 2.f ? 2.f  : (aq < 4.f ? 1.f : 0.5f);
        float qr = rintf(qv * rlsb) * lsb;          // RNE onto fp4 grid (exact)
        q[j] = __float2bfloat16(qr * scale);        // exact in bf16
    }
    reinterpret_cast<uint2*>(out)[t] = *reinterpret_cast<const uint2*>(q);
}

__global__ void __launch_bounds__(256) quant_mxfp4_fused_kernel(
    const float* __restrict__ a, __nv_bfloat16* __restrict__ aq,
    const float* __restrict__ w, __nv_bfloat16* __restrict__ wq,
    int aquads, int wquads)
{
    int t = blockIdx.x * blockDim.x + threadIdx.x;
    if (t < aquads)                quant_quad(a, aq, t);
    else if (t < aquads + wquads)  quant_quad(w, wq, t - aquads);
}

// ============================================================================
// bf16 GEMM via mma.sync: out[M,N] = Aq[M,K] @ Wq[N,K]^T + bias
// CTA tile 128x256x32, 256 threads (8 warps, 2x4), warp tile 64x64.
// 5-stage cp.async ring; fragments software-pipelined ACROSS the barrier:
//   load frag(ks=1) ; MMA(ks=0) ; wait+bar+prefetch ; load frag(next, ks=0) ;
//   MMA(ks=1)
// so every LDSM/barrier/cp.async phase hides under an MMA burst.
// Smem rows padded to 80B (conflict-free ldmatrix).
// ============================================================================
static constexpr int BM = 128;
static constexpr int BN = 256;
static constexpr int BK = 32;            // bf16 elems per K-stage
static constexpr int STAGES = 5;
static constexpr int ROW_H = 40;         // smem row stride in halves (80 B)
static constexpr int TILEA_B = BM * ROW_H * 2;        // 10240 bytes
static constexpr int TILEB_B = BN * ROW_H * 2;        // 20480 bytes
static constexpr int STAGE_B = TILEA_B + TILEB_B;     // 30720 bytes
static constexpr int SMEM_TOTAL = STAGES * STAGE_B;   // 153600 bytes

__global__ void __launch_bounds__(256, 1) mxfp4_gemm_kernel(
    const __nv_bfloat16* __restrict__ A,   // [M,K]
    const __nv_bfloat16* __restrict__ W,   // [N,K]
    const float* __restrict__ bias,        // [N]
    float* __restrict__ out,               // [M,N]
    int M, int N, int K)
{
    extern __shared__ __align__(16) char smem[];
    const uint32_t sb = smem_to_u32(smem);

    const int tid = threadIdx.x;
    const int wid = tid >> 5;
    const int lid = tid & 31;
    const int warp_m = wid & 1;           // 0..1 -> 64-row slab
    const int warp_n = wid >> 1;          // 0..3 -> 64-col slab
    const int m0 = blockIdx.y * BM;
    const int n0 = blockIdx.x * BN;

    // cp.async: A 512 chunks (2/thread), B 1024 chunks (4/thread)
    const int cc = tid & 3;               // 16B chunk within 64B row
    const int rr = tid >> 2;              // base row 0..63

    const __nv_bfloat16* Abase = A + (size_t)m0 * K;
    const __nv_bfloat16* Wbase = W + (size_t)n0 * K;

    auto prefetch = [&](int stage, int kk) {
        uint32_t sA = sb + stage * STAGE_B;
        uint32_t sB = sA + TILEA_B;
#pragma unroll
        for (int i = 0; i < 2; i++) {
            int r = rr + i * 64;
            CP_ASYNC16(sA + (uint32_t)(r * ROW_H + cc * 8) * 2,
                       Abase + (size_t)r * K + kk + cc * 8);
        }
#pragma unroll
        for (int i = 0; i < 4; i++) {
            int r = rr + i * 64;
            CP_ASYNC16(sB + (uint32_t)(r * ROW_H + cc * 8) * 2,
                       Wbase + (size_t)r * K + kk + cc * 8);
        }
    };

    float acc[4][8][4];
#pragma unroll
    for (int tm = 0; tm < 4; tm++)
#pragma unroll
        for (int nt = 0; nt < 8; nt++)
#pragma unroll
            for (int j = 0; j < 4; j++) acc[tm][nt][j] = 0.f;

    const int aRowBase = warp_m * 64;
    const int bRowBase = warp_n * 64;
    const int nK = K / BK;

    auto load_frags = [&](uint32_t sA, uint32_t sBm, int ks,
                          uint32_t af[4][4], uint32_t bf[8][2]) {
#pragma unroll
        for (int tm = 0; tm < 4; tm++) {
            int row = aRowBase + tm * 16 + (lid & 15);
            int col = ks * 16 + (lid >> 4) * 8;
            ldsm_x4(af[tm], sA + (uint32_t)(row * ROW_H + col) * 2);
        }
#pragma unroll
        for (int ntp = 0; ntp < 4; ntp++) {
            int g = lid >> 3;
            int row = bRowBase + ntp * 16 + (g >> 1) * 8 + (lid & 7);
            int col = ks * 16 + (g & 1) * 8;
            uint32_t r[4];
            ldsm_x4(r, sBm + (uint32_t)(row * ROW_H + col) * 2);
            bf[2 * ntp][0]     = r[0];
            bf[2 * ntp][1]     = r[1];
            bf[2 * ntp + 1][0] = r[2];
            bf[2 * ntp + 1][1] = r[3];
        }
    };

    // prologue: fill STAGES-1 stages, land stage 0, preload its ks=0 frags
#pragma unroll
    for (int s = 0; s < STAGES - 1; s++) {
        prefetch(s, s * BK);
        CP_COMMIT();
    }
    CP_WAIT(STAGES - 2);
    __syncthreads();

    uint32_t af[2][4][4];
    uint32_t bf[2][8][2];
    load_frags(sb, sb + TILEA_B, 0, af[0], bf[0]);

    int cur = 0;
    for (int kt = 0; kt < nK; kt++) {
        const uint32_t sA = sb + cur * STAGE_B;
        const uint32_t sBm = sA + TILEA_B;

        // LDSM for substep 1 — independent of the MMA burst below
        load_frags(sA, sBm, 1, af[1], bf[1]);

        // MMA substep 0 (covers the LDSM above + the barrier below)
#pragma unroll
        for (int tm = 0; tm < 4; tm++)
#pragma unroll
            for (int nt = 0; nt < 8; nt++)
                mma_16816(acc[tm][nt], af[0][tm], bf[0][nt]);

        // stage boundary: make stage kt+1 visible, refill the stage consumed
        // at kt-1 (all warps' LDSM reads of it ordered before this barrier)
        if (kt + 1 < nK) {
            CP_WAIT(STAGES - 3);
            __syncthreads();
            int wstage = cur + STAGES - 1;
            if (wstage >= STAGES) wstage -= STAGES;
            if (kt + STAGES - 1 < nK)
                prefetch(wstage, (kt + STAGES - 1) * BK);
            CP_COMMIT();

            int nstage = (cur + 1 == STAGES) ? 0 : cur + 1;
            uint32_t nA = sb + nstage * STAGE_B;
            load_frags(nA, nA + TILEA_B, 0, af[0], bf[0]);
        }

        // MMA substep 1 (covers the next-stage LDSM + cp.async issue above)
#pragma unroll
        for (int tm = 0; tm < 4; tm++)
#pragma unroll
            for (int nt = 0; nt < 8; nt++)
                mma_16816(acc[tm][nt], af[1][tm], bf[1][nt]);

        cur = (cur + 1 == STAGES) ? 0 : cur + 1;
    }

    // ---- epilogue: fused bias, float2 stores ----
    const int g = lid >> 2;               // 0..7
    const int tc = (lid & 3) * 2;         // 0,2,4,6
#pragma unroll
    for (int nt = 0; nt < 8; nt++) {
        int col = n0 + warp_n * 64 + nt * 8 + tc;
        float2 bv = *reinterpret_cast<const float2*>(bias + col);
#pragma unroll
        for (int tm = 0; tm < 4; tm++) {
            int row = m0 + warp_m * 64 + tm * 16 + g;
            float2 v0 = { acc[tm][nt][0] + bv.x, acc[tm][nt][1] + bv.y };
            float2 v1 = { acc[tm][nt][2] + bv.x, acc[tm][nt][3] + bv.y };
            *reinterpret_cast<float2*>(out + (size_t)row * N + col) = v0;
            *reinterpret_cast<float2*>(out + (size_t)(row + 8) * N + col) = v1;
        }
    }
}

// ============================================================================
// launch
// ============================================================================
extern "C" void kernel_launch(void* const* d_in, const int* in_sizes, int n_in,
                              void* d_out, int out_size)
{
    const float* inp  = (const float*)d_in[0];   // [B*S, K] fp32
    const float* w    = (const float*)d_in[1];   // [N, K]  fp32
    const float* bias = (const float*)d_in[2];   // [N]     fp32
    float* out = (float*)d_out;

    int N = in_sizes[2];
    int K = in_sizes[1] / N;
    int M = (int)((long long)in_sizes[0] / K);

    __nv_bfloat16 *Aq, *Wq;
    cudaGetSymbolAddress((void**)&Aq, g_Aq);
    cudaGetSymbolAddress((void**)&Wq, g_Wq);

    int aquads = (int)((long long)M * K / 4);
    int wquads = (int)((long long)N * K / 4);
    int tquads = aquads + wquads;
    quant_mxfp4_fused_kernel<<<(tquads + 255) / 256, 256>>>(
        inp, Aq, w, Wq, aquads, wquads);

    static bool attr_set = false;
    if (!attr_set) {
        cudaFuncSetAttribute(mxfp4_gemm_kernel,
                             cudaFuncAttributeMaxDynamicSharedMemorySize,
                             SMEM_TOTAL);
        attr_set = true;
    }

    dim3 grid(N / BN, M / BM);
    mxfp4_gemm_kernel<<<grid, 256, SMEM_TOTAL>>>(Aq, Wq, bias, out, M, N, K);
}

// round 11
// speedup vs baseline: 1.6047x; 1.2537x over previous
#include <cuda_runtime.h>
#include <cuda_bf16.h>
#include <cstdint>

// ============================================================================
// xFuserMXFP4Linear: fake-MXFP4 (e2m1 + E8M0 per-1x32-block scale) quant of
// A[M,K] and W[N,K], then fp32 GEMM out = Aq @ Wq^T + bias.
//
// Toolchain emits PTX for plain sm_103 => no tcgen05/TMA. Baseline tensor
// path: cp.async + ldmatrix + mma.sync.m16n8k16 (bf16 in, fp32 accum).
// Dequantized MXFP4 values are exact in bf16 => rel_err ~0.
//
// R10: best-known config (R5: 32x64 warps, 2 CTAs/SM for phase staggering,
// low reg pressure) + BK=64 (half the barrier frequency) + 3-stage ring.
// Overlap comes from 4 warps/SMSP across 2 independent CTAs, not from
// intra-warp scheduling.
// ============================================================================

// ---------------- device scratch (allowed: __device__ globals) --------------
__device__ __nv_bfloat16 g_Aq[8192u * 2048u];   // 32 MB
__device__ __nv_bfloat16 g_Wq[2048u * 2048u];   // 8 MB

// ============================================================================
// PTX helpers (baseline ISA only)
// ============================================================================
__device__ __forceinline__ uint32_t smem_to_u32(const void* smem_ptr) {
    uint32_t addr;
    asm("{ .reg .u64 tmp; cvta.to.shared.u64 tmp, %1; cvt.u32.u64 %0, tmp; }"
        : "=r"(addr) : "l"(smem_ptr));
    return addr;
}

#define CP_ASYNC16(smem_u32, gptr) \
    asm volatile("cp.async.cg.shared.global [%0], [%1], 16;\n" \
                 :: "r"(smem_u32), "l"(gptr))

#define CP_COMMIT() asm volatile("cp.async.commit_group;\n" ::: "memory")
#define CP_WAIT(n)  asm volatile("cp.async.wait_group %0;\n" :: "n"(n) : "memory")

__device__ __forceinline__ void ldsm_x4(uint32_t* r, uint32_t addr) {
    asm volatile("ldmatrix.sync.aligned.m8n8.x4.shared.b16 {%0,%1,%2,%3}, [%4];"
                 : "=r"(r[0]), "=r"(r[1]), "=r"(r[2]), "=r"(r[3]) : "r"(addr));
}

__device__ __forceinline__ void mma_16816(float* c, const uint32_t* a,
                                          const uint32_t* b) {
    asm volatile(
        "mma.sync.aligned.m16n8k16.row.col.f32.bf16.bf16.f32 "
        "{%0,%1,%2,%3}, {%4,%5,%6,%7}, {%8,%9}, {%0,%1,%2,%3};"
        : "+f"(c[0]), "+f"(c[1]), "+f"(c[2]), "+f"(c[3])
        : "r"(a[0]), "r"(a[1]), "r"(a[2]), "r"(a[3]), "r"(b[0]), "r"(b[1]));
}

// ============================================================================
// Quantize kernel (fused A+W): 8 threads per 1x32 block, one float4/thread.
// amax exponent from IEEE bits (exact; libdevice fallback for denormal/edge).
// ============================================================================
__device__ __forceinline__ void quant_quad(const float* __restrict__ x,
                                           __nv_bfloat16* __restrict__ out,
                                           int t)
{
    float4 v = reinterpret_cast<const float4*>(x)[t];
    float amax = fmaxf(fmaxf(fabsf(v.x), fabsf(v.y)),
                       fmaxf(fabsf(v.z), fabsf(v.w)));
    amax = fmaxf(amax, __shfl_xor_sync(0xFFFFFFFFu, amax, 1));
    amax = fmaxf(amax, __shfl_xor_sync(0xFFFFFFFFu, amax, 2));
    amax = fmaxf(amax, __shfl_xor_sync(0xFFFFFFFFu, amax, 4));

    float scale = 1.f, inv = 1.f;
    if (amax > 0.f) {
        uint32_t bits = __float_as_uint(amax);
        int e = (int)(bits >> 23);          // biased exponent
        if (e >= 3 && e <= 254) {
            // floor(log2(amax)) = e-127; scale = 2^(e-127-2); inv = 1/scale
            scale = __uint_as_float((uint32_t)(e - 2) << 23);
            inv   = __uint_as_float((uint32_t)(256 - e) << 23);
        } else {
            // denormal or near-overflow amax: exact libdevice fallback
            int ee;
            frexpf(fmaxf(amax, 1.17549435e-38f), &ee);
            scale = ldexpf(1.f, ee - 3);
            inv   = (ee >= -120) ? ldexpf(1.f, 3 - ee) : 0.f;
            if (inv == 0.f) {               // extreme underflow: divide path
                float in4[4] = {v.x, v.y, v.z, v.w};
                __nv_bfloat16 q[4];
#pragma unroll
                for (int j = 0; j < 4; j++) {
                    float qv = fminf(fmaxf(in4[j] / scale, -6.f), 6.f);
                    float aq = fabsf(qv);
                    float lsb  = aq < 2.f ? 0.5f : (aq < 4.f ? 1.f : 2.f);
                    float rlsb = aq < 2.f ? 2.f  : (aq < 4.f ? 1.f : 0.5f);
                    q[j] = __float2bfloat16(rintf(qv * rlsb) * lsb * scale);
                }
                reinterpret_cast<uint2*>(out)[t] =
                    *reinterpret_cast<const uint2*>(q);
                return;
            }
        }
    }

    float in4[4] = {v.x, v.y, v.z, v.w};
    __nv_bfloat16 q[4];
#pragma unroll
    for (int j = 0; j < 4; j++) {
        float qv = fminf(fmaxf(in4[j] * inv, -6.f), 6.f);
        float aq = fabsf(qv);
        // e2m1 ulp: 0.5 on [0,2), 1 on [2,4), 2 on [4,6]
        float lsb  = aq < 2.f ? 0.5f : (aq < 4.f ? 1.f : 2.f);
        float rlsb = aq < 2.f ? 2.f  : (aq < 4.f ? 1.f : 0.5f);
        float qr = rintf(qv * rlsb) * lsb;          // RNE onto fp4 grid (exact)
        q[j] = __float2bfloat16(qr * scale);        // exact in bf16
    }
    reinterpret_cast<uint2*>(out)[t] = *reinterpret_cast<const uint2*>(q);
}

__global__ void __launch_bounds__(256) quant_mxfp4_fused_kernel(
    const float* __restrict__ a, __nv_bfloat16* __restrict__ aq,
    const float* __restrict__ w, __nv_bfloat16* __restrict__ wq,
    int aquads, int wquads)
{
    int t = blockIdx.x * blockDim.x + threadIdx.x;
    if (t < aquads)                quant_quad(a, aq, t);
    else if (t < aquads + wquads)  quant_quad(w, wq, t - aquads);
}

// ============================================================================
// bf16 GEMM via mma.sync: out[M,N] = Aq[M,K] @ Wq[N,K]^T + bias
// CTA tile 128x128x64, 256 threads (8 warps, 4x2), warp tile 32x64.
// 2 CTAs/SM (launch_bounds 256,2) stagger barrier/LDSM phases across CTAs.
// 3-stage cp.async ring, ONE CP_WAIT+__syncthreads per 64-deep K-step.
// Rows padded to 144B (BK=64 data 128B + 16B) -> conflict-free ldmatrix.
// ============================================================================
static constexpr int BM = 128;
static constexpr int BN = 128;
static constexpr int BK = 64;            // bf16 elems per K-stage
static constexpr int STAGES = 3;
static constexpr int ROW_H = 72;         // smem row stride in halves (144 B)
static constexpr int TILE_B = 128 * ROW_H * 2;        // 18432 bytes
static constexpr int STAGE_B = 2 * TILE_B;            // A + B = 36864 bytes
static constexpr int SMEM_TOTAL = STAGES * STAGE_B;   // 110592 bytes

__global__ void __launch_bounds__(256, 2) mxfp4_gemm_kernel(
    const __nv_bfloat16* __restrict__ A,   // [M,K]
    const __nv_bfloat16* __restrict__ W,   // [N,K]
    const float* __restrict__ bias,        // [N]
    float* __restrict__ out,               // [M,N]
    int M, int N, int K)
{
    extern __shared__ __align__(16) char smem[];
    const uint32_t sb = smem_to_u32(smem);

    const int tid = threadIdx.x;
    const int wid = tid >> 5;
    const int lid = tid & 31;
    const int warp_m = wid & 3;           // 0..3 -> 32-row slab
    const int warp_n = wid >> 2;          // 0..1 -> 64-col slab
    const int m0 = blockIdx.y * BM;
    const int n0 = blockIdx.x * BN;

    // cp.async: each tile = 128 rows x 8 chunks(16B) = 1024 chunks; 256 thr
    // handle A(4/thread) + B(4/thread).
    const int cc = tid & 7;               // 16B chunk within 128B row data
    const int rr = tid >> 3;              // base row 0..31

    const __nv_bfloat16* Abase = A + (size_t)m0 * K;
    const __nv_bfloat16* Wbase = W + (size_t)n0 * K;

    auto prefetch = [&](int stage, int kk) {
        uint32_t sA = sb + stage * STAGE_B;
        uint32_t sB = sA + TILE_B;
#pragma unroll
        for (int i = 0; i < 4; i++) {
            int r = rr + i * 32;
            CP_ASYNC16(sA + (uint32_t)(r * ROW_H + cc * 8) * 2,
                       Abase + (size_t)r * K + kk + cc * 8);
            CP_ASYNC16(sB + (uint32_t)(r * ROW_H + cc * 8) * 2,
                       Wbase + (size_t)r * K + kk + cc * 8);
        }
    };

    float acc[2][8][4];
#pragma unroll
    for (int tm = 0; tm < 2; tm++)
#pragma unroll
        for (int nt = 0; nt < 8; nt++)
#pragma unroll
            for (int j = 0; j < 4; j++) acc[tm][nt][j] = 0.f;

    const int aRowBase = warp_m * 32;
    const int bRowBase = warp_n * 64;
    const int nK = K / BK;

    // prologue: fill STAGES-1 stages
#pragma unroll
    for (int s = 0; s < STAGES - 1; s++) {
        prefetch(s, s * BK);
        CP_COMMIT();
    }

    int cur = 0;
    for (int kt = 0; kt < nK; kt++) {
        CP_WAIT(STAGES - 2);
        __syncthreads();

        // refill the stage consumed at kt-1 (all LDSM reads of it were
        // ordered before this barrier)
        if (kt + STAGES - 1 < nK) {
            int wstage = cur + STAGES - 1;
            if (wstage >= STAGES) wstage -= STAGES;
            prefetch(wstage, (kt + STAGES - 1) * BK);
        }
        CP_COMMIT();

        const uint32_t sA = sb + cur * STAGE_B;
        const uint32_t sBm = sA + TILE_B;

        // ---- 4 substeps of k=16; frags loaded per substep; overlap across
        // warps/CTAs (4 warps/SMSP) rather than within a warp ----
#pragma unroll
        for (int ks = 0; ks < 4; ks++) {
            uint32_t af[2][4];   // [tm][4]
            uint32_t bf[8][2];   // [nt][2]
#pragma unroll
            for (int tm = 0; tm < 2; tm++) {
                int row = aRowBase + tm * 16 + (lid & 15);
                int col = ks * 16 + (lid >> 4) * 8;
                ldsm_x4(af[tm], sA + (uint32_t)(row * ROW_H + col) * 2);
            }
#pragma unroll
            for (int ntp = 0; ntp < 4; ntp++) {
                int g = lid >> 3;
                int row = bRowBase + ntp * 16 + (g >> 1) * 8 + (lid & 7);
                int col = ks * 16 + (g & 1) * 8;
                uint32_t r[4];
                ldsm_x4(r, sBm + (uint32_t)(row * ROW_H + col) * 2);
                bf[2 * ntp][0]     = r[0];
                bf[2 * ntp][1]     = r[1];
                bf[2 * ntp + 1][0] = r[2];
                bf[2 * ntp + 1][1] = r[3];
            }
            // pin LDSM issue point: memory ops may not sink past this
            asm volatile("" ::: "memory");

#pragma unroll
            for (int tm = 0; tm < 2; tm++)
#pragma unroll
                for (int nt = 0; nt < 8; nt++)
                    mma_16816(acc[tm][nt], af[tm], bf[nt]);
        }

        if (++cur == STAGES) cur = 0;
    }

    // ---- epilogue: fused bias, float2 stores ----
    const int g = lid >> 2;               // 0..7
    const int tc = (lid & 3) * 2;         // 0,2,4,6
#pragma unroll
    for (int nt = 0; nt < 8; nt++) {
        int col = n0 + warp_n * 64 + nt * 8 + tc;
        float2 bv = *reinterpret_cast<const float2*>(bias + col);
#pragma unroll
        for (int tm = 0; tm < 2; tm++) {
            int row = m0 + warp_m * 32 + tm * 16 + g;
            float2 v0 = { acc[tm][nt][0] + bv.x, acc[tm][nt][1] + bv.y };
            float2 v1 = { acc[tm][nt][2] + bv.x, acc[tm][nt][3] + bv.y };
            *reinterpret_cast<float2*>(out + (size_t)row * N + col) = v0;
            *reinterpret_cast<float2*>(out + (size_t)(row + 8) * N + col) = v1;
        }
    }
}

// ============================================================================
// launch
// ============================================================================
extern "C" void kernel_launch(void* const* d_in, const int* in_sizes, int n_in,
                              void* d_out, int out_size)
{
    const float* inp  = (const float*)d_in[0];   // [B*S, K] fp32
    const float* w    = (const float*)d_in[1];   // [N, K]  fp32
    const float* bias = (const float*)d_in[2];   // [N]     fp32
    float* out = (float*)d_out;

    int N = in_sizes[2];
    int K = in_sizes[1] / N;
    int M = (int)((long long)in_sizes[0] / K);

    __nv_bfloat16 *Aq, *Wq;
    cudaGetSymbolAddress((void**)&Aq, g_Aq);
    cudaGetSymbolAddress((void**)&Wq, g_Wq);

    int aquads = (int)((long long)M * K / 4);
    int wquads = (int)((long long)N * K / 4);
    int tquads = aquads + wquads;
    quant_mxfp4_fused_kernel<<<(tquads + 255) / 256, 256>>>(
        inp, Aq, w, Wq, aquads, wquads);

    static bool attr_set = false;
    if (!attr_set) {
        cudaFuncSetAttribute(mxfp4_gemm_kernel,
                             cudaFuncAttributeMaxDynamicSharedMemorySize,
                             SMEM_TOTAL);
        attr_set = true;
    }

    dim3 grid(N / BN, M / BM);
    mxfp4_gemm_kernel<<<grid, 256, SMEM_TOTAL>>>(Aq, Wq, bias, out, M, N, K);
}